// round 1
// baseline (speedup 1.0000x reference)
#include <cuda_runtime.h>
#include <cstdint>

#define M_DIM 4096
#define N_DIM 8192
#define K_DIM 256

// Scratch (allocation-free rule: __device__ globals)
__device__ float g_out_b[M_DIM * K_DIM];   // branch output, tf32-rounded
__device__ float g_out_t[N_DIM * K_DIM];   // trunk output, tf32-rounded
__device__ float g_bias[N_DIM];            // per-column bias (fp32)

__device__ __forceinline__ float to_tf32(float x) {
    uint32_t u;
    asm("cvt.rna.tf32.f32 %0, %1;" : "=r"(u) : "f"(x));
    return __uint_as_float(u);
}

// ---------------------------------------------------------------------------
// Kernel 1: Branch MLP. One warp per row of noise. Lane j owns hidden unit j.
// ---------------------------------------------------------------------------
__global__ __launch_bounds__(256) void branch_kernel(
    const float* __restrict__ noise,
    const float* __restrict__ W1, const float* __restrict__ b1,
    const float* __restrict__ W2, const float* __restrict__ b2,
    const float* __restrict__ W3, const float* __restrict__ b3,
    const float* __restrict__ W4, const float* __restrict__ b4,
    const float* __restrict__ W5, const float* __restrict__ b5)
{
    __shared__ float sW1[128 * 32];
    __shared__ float sW2[32 * 32];
    __shared__ float sW3[32 * 32];
    __shared__ float sW4[32 * 32];
    __shared__ float sb[4 * 32];

    int tid = threadIdx.x;
    for (int i = tid; i < 128 * 32; i += 256) sW1[i] = W1[i];
    for (int i = tid; i < 32 * 32; i += 256) {
        sW2[i] = W2[i]; sW3[i] = W3[i]; sW4[i] = W4[i];
    }
    if (tid < 32) {
        sb[tid] = b1[tid]; sb[32 + tid] = b2[tid];
        sb[64 + tid] = b3[tid]; sb[96 + tid] = b4[tid];
    }
    __syncthreads();

    int lane = tid & 31;
    int row  = blockIdx.x * 8 + (tid >> 5);

    const float* x = noise + row * 128;
    float x0 = x[lane], x1 = x[lane + 32], x2 = x[lane + 64], x3 = x[lane + 96];

    // layer 1: 128 -> 32, lane = output unit
    float acc = sb[lane];
    #pragma unroll
    for (int k = 0; k < 128; k++) {
        float src = (k < 32) ? x0 : (k < 64) ? x1 : (k < 96) ? x2 : x3;
        float xk = __shfl_sync(0xffffffffu, src, k & 31);
        acc = fmaf(xk, sW1[k * 32 + lane], acc);
    }
    float h = tanhf(acc);

    // layers 2..4: 32 -> 32
    {
        float a = sb[32 + lane];
        #pragma unroll
        for (int k = 0; k < 32; k++)
            a = fmaf(__shfl_sync(0xffffffffu, h, k), sW2[k * 32 + lane], a);
        h = tanhf(a);
    }
    {
        float a = sb[64 + lane];
        #pragma unroll
        for (int k = 0; k < 32; k++)
            a = fmaf(__shfl_sync(0xffffffffu, h, k), sW3[k * 32 + lane], a);
        h = tanhf(a);
    }
    {
        float a = sb[96 + lane];
        #pragma unroll
        for (int k = 0; k < 32; k++)
            a = fmaf(__shfl_sync(0xffffffffu, h, k), sW4[k * 32 + lane], a);
        h = tanhf(a);
    }

    // head: 32 -> 256, lane owns outputs {lane + 32*i}. W5/b5 via L1.
    float o[8];
    #pragma unroll
    for (int i = 0; i < 8; i++) o[i] = b5[lane + 32 * i];
    #pragma unroll
    for (int k = 0; k < 32; k++) {
        float hk = __shfl_sync(0xffffffffu, h, k);
        const float* w = W5 + k * 256 + lane;
        #pragma unroll
        for (int i = 0; i < 8; i++) o[i] = fmaf(hk, w[32 * i], o[i]);
    }
    float* op = g_out_b + row * 256 + lane;
    #pragma unroll
    for (int i = 0; i < 8; i++) op[32 * i] = to_tf32(o[i]);
}

// ---------------------------------------------------------------------------
// Kernel 2: Trunk. out_t[j][p] = coords[j]·Wc[:,p] + bc[p]; bias[j] from Wm.
// ---------------------------------------------------------------------------
__global__ __launch_bounds__(256) void trunk_kernel(
    const float* __restrict__ coords,
    const float* __restrict__ Wc, const float* __restrict__ bc,
    const float* __restrict__ Wm, const float* __restrict__ bm)
{
    int idx = blockIdx.x * 256 + threadIdx.x;
    int j = idx >> 8, p = idx & 255;
    float c0 = coords[2 * j], c1 = coords[2 * j + 1];
    float v = fmaf(c0, Wc[p], fmaf(c1, Wc[256 + p], bc[p]));
    g_out_t[idx] = to_tf32(v);
    if (p == 0)
        g_bias[j] = fmaf(c0, Wm[0], fmaf(c1, Wm[1], bm[0]));
}

// ---------------------------------------------------------------------------
// Kernel 3: g = out_b @ out_t^T + bias, via mma.sync m16n8k8 tf32.
// BM=BN=128, BK=16, 256 threads, 8 warps (2x4), warp tile 64x32.
// Smem row stride 20 words: fragment-load bank = (20g + t) mod 32 -> all 32
// lanes distinct -> conflict-free LDS.
// ---------------------------------------------------------------------------
#define BM 128
#define BN 128
#define BK 16
#define NKT (K_DIM / BK)     // 16
#define LDST 20              // smem row stride (words)

__device__ __forceinline__ void mma_tf32(float* d, const uint32_t* a, const uint32_t* b) {
    asm volatile(
        "mma.sync.aligned.m16n8k8.row.col.f32.tf32.tf32.f32 "
        "{%0,%1,%2,%3}, {%4,%5,%6,%7}, {%8,%9}, {%0,%1,%2,%3};"
        : "+f"(d[0]), "+f"(d[1]), "+f"(d[2]), "+f"(d[3])
        : "r"(a[0]), "r"(a[1]), "r"(a[2]), "r"(a[3]),
          "r"(b[0]), "r"(b[1]));
}

__device__ __forceinline__ void cpasync16(uint32_t dst, const float* src) {
    asm volatile("cp.async.cg.shared.global [%0], [%1], 16;" :: "r"(dst), "l"(src));
}

__global__ __launch_bounds__(256) void gemm_kernel(float* __restrict__ out) {
    __shared__ __align__(16) float As[2][BM][LDST];
    __shared__ __align__(16) float Bs[2][BN][LDST];

    int tid  = threadIdx.x;
    int bm0  = blockIdx.y * BM;
    int bn0  = blockIdx.x * BN;

    // loader: thread -> (row = tid>>2 and +64, k-chunk = (tid&3)*4)
    int lrow = tid >> 2;
    int lk4  = (tid & 3) << 2;
    const float* agp = &g_out_b[(bm0 + lrow) * K_DIM + lk4];
    const float* bgp = &g_out_t[(bn0 + lrow) * K_DIM + lk4];

    uint32_t sa0[2], sa1[2], sb0[2], sb1[2];
    #pragma unroll
    for (int s = 0; s < 2; s++) {
        sa0[s] = (uint32_t)__cvta_generic_to_shared(&As[s][lrow][lk4]);
        sa1[s] = (uint32_t)__cvta_generic_to_shared(&As[s][lrow + 64][lk4]);
        sb0[s] = (uint32_t)__cvta_generic_to_shared(&Bs[s][lrow][lk4]);
        sb1[s] = (uint32_t)__cvta_generic_to_shared(&Bs[s][lrow + 64][lk4]);
    }

    auto load_stage = [&](int s, int kt) {
        int kg = kt * BK;
        cpasync16(sa0[s], agp + kg);
        cpasync16(sa1[s], agp + 64 * K_DIM + kg);
        cpasync16(sb0[s], bgp + kg);
        cpasync16(sb1[s], bgp + 64 * K_DIM + kg);
        asm volatile("cp.async.commit_group;");
    };

    load_stage(0, 0);
    load_stage(1, 1);

    int wid  = tid >> 5;
    int lane = tid & 31;
    int wm   = (wid >> 2) * 64;   // warp m-offset within tile
    int wn   = (wid & 3) * 32;    // warp n-offset within tile
    int g    = lane >> 2;         // groupID
    int t    = lane & 3;          // threadID_in_group

    float acc[4][4][4];
    #pragma unroll
    for (int mt = 0; mt < 4; mt++)
        #pragma unroll
        for (int nt = 0; nt < 4; nt++)
            #pragma unroll
            for (int r = 0; r < 4; r++) acc[mt][nt][r] = 0.0f;

    for (int kt = 0; kt < NKT; ++kt) {
        if (kt == NKT - 1) asm volatile("cp.async.wait_group 0;");
        else               asm volatile("cp.async.wait_group 1;");
        __syncthreads();
        int s = kt & 1;

        #pragma unroll
        for (int kc = 0; kc < 2; kc++) {
            int kb = kc * 8;
            uint32_t af[4][4];
            uint32_t bf[4][2];
            #pragma unroll
            for (int mt = 0; mt < 4; mt++) {
                int m = wm + mt * 16;
                af[mt][0] = __float_as_uint(As[s][m + g    ][kb + t    ]);
                af[mt][1] = __float_as_uint(As[s][m + g + 8][kb + t    ]);
                af[mt][2] = __float_as_uint(As[s][m + g    ][kb + t + 4]);
                af[mt][3] = __float_as_uint(As[s][m + g + 8][kb + t + 4]);
            }
            #pragma unroll
            for (int nt = 0; nt < 4; nt++) {
                int n = wn + nt * 8;
                bf[nt][0] = __float_as_uint(Bs[s][n + g][kb + t    ]);
                bf[nt][1] = __float_as_uint(Bs[s][n + g][kb + t + 4]);
            }
            #pragma unroll
            for (int mt = 0; mt < 4; mt++)
                #pragma unroll
                for (int nt = 0; nt < 4; nt++)
                    mma_tf32(acc[mt][nt], af[mt], bf[nt]);
        }
        __syncthreads();
        if (kt + 2 < NKT) load_stage(s, kt + 2);
    }

    // epilogue: += bias[col], store float2 per (row, col-pair)
    #pragma unroll
    for (int nt = 0; nt < 4; nt++) {
        int col = bn0 + wn + nt * 8 + t * 2;
        float2 bb = *(const float2*)&g_bias[col];
        #pragma unroll
        for (int mt = 0; mt < 4; mt++) {
            int row = bm0 + wm + mt * 16 + g;
            float2 v0 = make_float2(acc[mt][nt][0] + bb.x, acc[mt][nt][1] + bb.y);
            float2 v1 = make_float2(acc[mt][nt][2] + bb.x, acc[mt][nt][3] + bb.y);
            *(float2*)&out[row * N_DIM + col]       = v0;
            *(float2*)&out[(row + 8) * N_DIM + col] = v1;
        }
    }
}

// ---------------------------------------------------------------------------
extern "C" void kernel_launch(void* const* d_in, const int* in_sizes, int n_in,
                              void* d_out, int out_size) {
    const float* noise  = (const float*)d_in[0];
    const float* coords = (const float*)d_in[1];
    const float* W1 = (const float*)d_in[2];  const float* b1 = (const float*)d_in[3];
    const float* W2 = (const float*)d_in[4];  const float* b2 = (const float*)d_in[5];
    const float* W3 = (const float*)d_in[6];  const float* b3 = (const float*)d_in[7];
    const float* W4 = (const float*)d_in[8];  const float* b4 = (const float*)d_in[9];
    const float* W5 = (const float*)d_in[10]; const float* b5 = (const float*)d_in[11];
    const float* Wc = (const float*)d_in[12]; const float* bc = (const float*)d_in[13];
    const float* Wm = (const float*)d_in[14]; const float* bm = (const float*)d_in[15];
    float* out = (float*)d_out;

    branch_kernel<<<M_DIM / 8, 256>>>(noise, W1, b1, W2, b2, W3, b3, W4, b4, W5, b5);
    trunk_kernel<<<N_DIM, 256>>>(coords, Wc, bc, Wm, bm);
    dim3 grid(N_DIM / BN, M_DIM / BM);
    gemm_kernel<<<grid, 256>>>(out);
}

// round 3
// speedup vs baseline: 1.4799x; 1.4799x over previous
#include <cuda_runtime.h>
#include <cstdint>

#define M_DIM 4096
#define N_DIM 8192
#define K_DIM 256

// ---------------------------------------------------------------------------
// Scratch, stored as PRE-PACKED mma fragment chunks.
// A: [m_tile 32][kt 16][i16*2+kc : 16 regions][32 lanes][4 floats]  (8KB/kt)
// B: [n_tile 32][kt 16][jp*2+kc  : 32 regions][32 lanes][4 floats]  (16KB/kt)
// ---------------------------------------------------------------------------
__device__ __align__(128) float g_out_b_pk[M_DIM * K_DIM];   // 4 MB
__device__ __align__(128) float g_out_t_pk[N_DIM * K_DIM];   // 8 MB
__device__ float g_bias[N_DIM];

__device__ __forceinline__ float to_tf32(float x) {
    uint32_t u;
    asm("cvt.rna.tf32.f32 %0, %1;" : "=r"(u) : "f"(x));
    return __uint_as_float(u);
}

// packed index for A element (row in [0,4096), k in [0,256))
__device__ __forceinline__ int a_pack_idx(int row, int k) {
    int tm = row >> 7, r = row & 127;
    int kt = k >> 4, kk = k & 15, kc = kk >> 3, k7 = kk & 7;
    int t = k7 & 3, tk = k7 >> 2;
    int i16 = r >> 4, g = r & 7, half = (r >> 3) & 1;
    return tm * 32768 + kt * 2048 + (i16 * 2 + kc) * 128 + (g * 4 + t) * 4
         + (half + 2 * tk);
}

// packed index for B element (nrow in [0,8192), k in [0,256))
__device__ __forceinline__ int b_pack_idx(int nrow, int k) {
    int tn = nrow >> 8, r = nrow & 255;
    int kt = k >> 4, kk = k & 15, kc = kk >> 3, k7 = kk & 7;
    int t = k7 & 3, tk = k7 >> 2;
    int jp = r >> 4, j1 = (r >> 3) & 1, g = r & 7;
    return tn * 65536 + kt * 4096 + (jp * 2 + kc) * 128 + (g * 4 + t) * 4
         + (j1 * 2 + tk);
}

// ---------------------------------------------------------------------------
// PTX helpers
// ---------------------------------------------------------------------------
__device__ __forceinline__ uint32_t smem_u32(const void* p) {
    uint32_t a;
    asm("{ .reg .u64 t; cvta.to.shared.u64 t, %1; cvt.u32.u64 %0, t; }" : "=r"(a) : "l"(p));
    return a;
}

#define MBARRIER_INIT(addr, cnt) \
    asm volatile("mbarrier.init.shared.b64 [%0], %1;" :: "r"(addr), "r"(cnt) : "memory")
#define MBARRIER_EXPECT_TX(addr, bytes) \
    asm volatile("mbarrier.arrive.expect_tx.shared.b64 _, [%0], %1;" :: "r"(addr), "r"(bytes) : "memory")
#define MBARRIER_ARRIVE(addr) \
    asm volatile("mbarrier.arrive.shared.b64 _, [%0];" :: "r"(addr) : "memory")

#define MBAR_WAIT(addr, parity) do {                                         \
    asm volatile("{\n\t.reg .pred P;\n\t"                                    \
        "W%=:\n\t"                                                           \
        "mbarrier.try_wait.parity.acquire.cta.shared::cta.b64 P, [%0], %1, 0x989680;\n\t" \
        "@P bra.uni D%=;\n\t bra.uni W%=;\n\tD%=:\n\t}"                      \
        :: "r"(addr), "r"(parity) : "memory");                               \
} while (0)

#define MBAR_WAIT_RELAXED(addr, parity) do {                                 \
    asm volatile("{\n\t.reg .pred P;\n\t"                                    \
        "W%=:\n\t"                                                           \
        "mbarrier.try_wait.parity.relaxed.cta.shared::cta.b64 P, [%0], %1, 0x989680;\n\t" \
        "@P bra.uni D%=;\n\t bra.uni W%=;\n\tD%=:\n\t}"                      \
        :: "r"(addr), "r"(parity) : "memory");                               \
} while (0)

__device__ __forceinline__ void bulk_g2s(uint32_t dst, const void* src, uint32_t bytes,
                                         uint32_t mbar) {
    asm volatile(
        "cp.async.bulk.shared::cluster.global.mbarrier::complete_tx::bytes [%0], [%1], %2, [%3];"
        :: "r"(dst), "l"(src), "r"(bytes), "r"(mbar) : "memory");
}

__device__ __forceinline__ void mma_tf32(float* d, float4 a, float b0, float b1) {
    asm volatile(
        "mma.sync.aligned.m16n8k8.row.col.f32.tf32.tf32.f32 "
        "{%0,%1,%2,%3}, {%4,%5,%6,%7}, {%8,%9}, {%0,%1,%2,%3};"
        : "+f"(d[0]), "+f"(d[1]), "+f"(d[2]), "+f"(d[3])
        : "r"(__float_as_uint(a.x)), "r"(__float_as_uint(a.y)),
          "r"(__float_as_uint(a.z)), "r"(__float_as_uint(a.w)),
          "r"(__float_as_uint(b0)), "r"(__float_as_uint(b1)));
}

// ---------------------------------------------------------------------------
// Kernel 1: Branch MLP. 512 threads, 16 rows/block.
// ---------------------------------------------------------------------------
__global__ __launch_bounds__(512) void branch_kernel(
    const float* __restrict__ noise,
    const float* __restrict__ W1, const float* __restrict__ b1,
    const float* __restrict__ W2, const float* __restrict__ b2,
    const float* __restrict__ W3, const float* __restrict__ b3,
    const float* __restrict__ W4, const float* __restrict__ b4,
    const float* __restrict__ W5, const float* __restrict__ b5)
{
    __shared__ float sW1[128 * 32];
    __shared__ float sW2[32 * 32];
    __shared__ float sW3[32 * 32];
    __shared__ float sW4[32 * 32];
    __shared__ float sb[4 * 32];
    __shared__ float hbuf[16][32];

    int tid = threadIdx.x;
    for (int i = tid; i < 128 * 32; i += 512) sW1[i] = W1[i];
    for (int i = tid; i < 32 * 32; i += 512) {
        sW2[i] = W2[i]; sW3[i] = W3[i]; sW4[i] = W4[i];
    }
    if (tid < 32) {
        sb[tid] = b1[tid]; sb[32 + tid] = b2[tid];
        sb[64 + tid] = b3[tid]; sb[96 + tid] = b4[tid];
    }
    __syncthreads();

    int lane = tid & 31;
    int wid  = tid >> 5;
    int row  = blockIdx.x * 16 + wid;

    const float* x = noise + row * 128;
    float x0 = x[lane], x1 = x[lane + 32], x2 = x[lane + 64], x3 = x[lane + 96];

    float a0 = sb[lane], a1 = 0.f, a2 = 0.f, a3 = 0.f;
    #pragma unroll
    for (int k = 0; k < 32; k++) {
        float v0 = __shfl_sync(0xffffffffu, x0, k);
        float v1 = __shfl_sync(0xffffffffu, x1, k);
        float v2 = __shfl_sync(0xffffffffu, x2, k);
        float v3 = __shfl_sync(0xffffffffu, x3, k);
        a0 = fmaf(v0, sW1[k * 32 + lane], a0);
        a1 = fmaf(v1, sW1[(k + 32) * 32 + lane], a1);
        a2 = fmaf(v2, sW1[(k + 64) * 32 + lane], a2);
        a3 = fmaf(v3, sW1[(k + 96) * 32 + lane], a3);
    }
    float h = tanhf((a0 + a1) + (a2 + a3));

    {
        float a = sb[32 + lane];
        #pragma unroll
        for (int k = 0; k < 32; k++)
            a = fmaf(__shfl_sync(0xffffffffu, h, k), sW2[k * 32 + lane], a);
        h = tanhf(a);
    }
    {
        float a = sb[64 + lane];
        #pragma unroll
        for (int k = 0; k < 32; k++)
            a = fmaf(__shfl_sync(0xffffffffu, h, k), sW3[k * 32 + lane], a);
        h = tanhf(a);
    }
    {
        float a = sb[96 + lane];
        #pragma unroll
        for (int k = 0; k < 32; k++)
            a = fmaf(__shfl_sync(0xffffffffu, h, k), sW4[k * 32 + lane], a);
        h = tanhf(a);
    }
    hbuf[wid][lane] = h;
    __syncthreads();

    // head: 32 -> 256, block-cooperative. Thread = (col, row-half of 8).
    int c  = tid & 255;
    int rh = tid >> 8;       // 0 or 1
    float o[8];
    float bias5 = b5[c];
    #pragma unroll
    for (int i = 0; i < 8; i++) o[i] = bias5;
    #pragma unroll
    for (int k = 0; k < 32; k++) {
        float w = W5[k * 256 + c];
        #pragma unroll
        for (int i = 0; i < 8; i++)
            o[i] = fmaf(hbuf[rh * 8 + i][k], w, o[i]);
    }
    #pragma unroll
    for (int i = 0; i < 8; i++) {
        int r = blockIdx.x * 16 + rh * 8 + i;
        g_out_b_pk[a_pack_idx(r, c)] = to_tf32(o[i]);
    }
}

// ---------------------------------------------------------------------------
// Kernel 2: Trunk -> packed B fragments + bias vector.
// ---------------------------------------------------------------------------
__global__ __launch_bounds__(256) void trunk_kernel(
    const float* __restrict__ coords,
    const float* __restrict__ Wc, const float* __restrict__ bc,
    const float* __restrict__ Wm, const float* __restrict__ bm)
{
    int j = blockIdx.x;        // output column (n index)
    int p = threadIdx.x;       // POD mode (k index)
    float c0 = coords[2 * j], c1 = coords[2 * j + 1];
    float v = fmaf(c0, Wc[p], fmaf(c1, Wc[256 + p], bc[p]));
    g_out_t_pk[b_pack_idx(j, p)] = to_tf32(v);
    if (p == 0)
        g_bias[j] = fmaf(c0, Wm[0], fmaf(c1, Wm[1], bm[0]));
}

// ---------------------------------------------------------------------------
// Kernel 3: GEMM via mma.sync tf32, packed fragments, 4-stage bulk pipeline.
// CTA 128x256, 8 warps (2x4), warp tile 64x64.
// ---------------------------------------------------------------------------
#define A_STG 8192
#define B_STG 16384
#define SMEM_TOTAL (128 + 4 * (A_STG + B_STG))   // 98432

__global__ __launch_bounds__(256, 1) void gemm_tc_kernel(float* __restrict__ out) {
    extern __shared__ __align__(128) char smem[];
    uint32_t sbb   = smem_u32(smem);
    uint32_t fullb = sbb;         // 4 x 8B
    uint32_t emptb = sbb + 32;    // 4 x 8B
    const int AS_OFF = 128;
    const int BS_OFF = 128 + 4 * A_STG;

    int tid  = threadIdx.x;
    int wid  = tid >> 5, lane = tid & 31;
    int g    = lane >> 2, t = lane & 3;
    int bm0  = blockIdx.y * 128;
    int bn0  = blockIdx.x * 256;

    if (tid == 0) {
        #pragma unroll
        for (int s = 0; s < 4; s++) {
            MBARRIER_INIT(fullb + s * 8, 1);
            MBARRIER_INIT(emptb + s * 8, 8);
        }
    }
    __syncthreads();

    const float* Ag = g_out_b_pk + blockIdx.y * 32768;
    const float* Bg = g_out_t_pk + blockIdx.x * 65536;

    if (tid == 0) {
        #pragma unroll
        for (int s = 0; s < 4; s++) {
            MBARRIER_EXPECT_TX(fullb + s * 8, A_STG + B_STG);
            bulk_g2s(sbb + AS_OFF + s * A_STG, Ag + s * 2048, A_STG, fullb + s * 8);
            bulk_g2s(sbb + BS_OFF + s * B_STG, Bg + s * 4096, B_STG, fullb + s * 8);
        }
    }

    float acc[4][8][4];
    #pragma unroll
    for (int mt = 0; mt < 4; mt++)
        #pragma unroll
        for (int nt = 0; nt < 8; nt++)
            #pragma unroll
            for (int r = 0; r < 4; r++) acc[mt][nt][r] = 0.0f;

    int a_warp = (wid >> 2) * 4096;   // (wid>>2)*4 i16-blocks * 1024B
    int b_warp = (wid & 3) * 4096;    // (wid&3)*4  jp-blocks  * 1024B

    for (int kt = 0; kt < 16; ++kt) {
        int s  = kt & 3;
        int ph = (kt >> 2) & 1;
        MBAR_WAIT(fullb + s * 8, ph);

        const char* As_s = smem + AS_OFF + s * A_STG + a_warp + lane * 16;
        const char* Bs_s = smem + BS_OFF + s * B_STG + b_warp + lane * 16;

        #pragma unroll
        for (int kc = 0; kc < 2; kc++) {
            float4 afv[4], bfv[4];
            #pragma unroll
            for (int mt = 0; mt < 4; mt++)
                afv[mt] = *(const float4*)(As_s + (mt * 2 + kc) * 512);
            #pragma unroll
            for (int p = 0; p < 4; p++)
                bfv[p] = *(const float4*)(Bs_s + (p * 2 + kc) * 512);
            #pragma unroll
            for (int mt = 0; mt < 4; mt++)
                #pragma unroll
                for (int p = 0; p < 4; p++) {
                    mma_tf32(acc[mt][2 * p],     afv[mt], bfv[p].x, bfv[p].y);
                    mma_tf32(acc[mt][2 * p + 1], afv[mt], bfv[p].z, bfv[p].w);
                }
        }

        if (lane == 0) MBARRIER_ARRIVE(emptb + s * 8);
        if (tid == 0 && kt < 12) {
            MBAR_WAIT_RELAXED(emptb + s * 8, ph);
            int ktp = kt + 4;
            MBARRIER_EXPECT_TX(fullb + s * 8, A_STG + B_STG);
            bulk_g2s(sbb + AS_OFF + s * A_STG, Ag + ktp * 2048, A_STG, fullb + s * 8);
            bulk_g2s(sbb + BS_OFF + s * B_STG, Bg + ktp * 4096, B_STG, fullb + s * 8);
        }
    }

    // epilogue: += bias[col], store float2 pairs
    int wm = (wid >> 2) * 64, wn = (wid & 3) * 64;
    #pragma unroll
    for (int nt = 0; nt < 8; nt++) {
        int col = bn0 + wn + nt * 8 + t * 2;
        float2 bb = *(const float2*)&g_bias[col];
        #pragma unroll
        for (int mt = 0; mt < 4; mt++) {
            int row = bm0 + wm + mt * 16 + g;
            float2 v0 = make_float2(acc[mt][nt][0] + bb.x, acc[mt][nt][1] + bb.y);
            float2 v1 = make_float2(acc[mt][nt][2] + bb.x, acc[mt][nt][3] + bb.y);
            *(float2*)&out[(size_t)row * N_DIM + col]       = v0;
            *(float2*)&out[(size_t)(row + 8) * N_DIM + col] = v1;
        }
    }
}

// ---------------------------------------------------------------------------
extern "C" void kernel_launch(void* const* d_in, const int* in_sizes, int n_in,
                              void* d_out, int out_size) {
    const float* noise  = (const float*)d_in[0];
    const float* coords = (const float*)d_in[1];
    const float* W1 = (const float*)d_in[2];  const float* b1 = (const float*)d_in[3];
    const float* W2 = (const float*)d_in[4];  const float* b2 = (const float*)d_in[5];
    const float* W3 = (const float*)d_in[6];  const float* b3 = (const float*)d_in[7];
    const float* W4 = (const float*)d_in[8];  const float* b4 = (const float*)d_in[9];
    const float* W5 = (const float*)d_in[10]; const float* b5 = (const float*)d_in[11];
    const float* Wc = (const float*)d_in[12]; const float* bc = (const float*)d_in[13];
    const float* Wm = (const float*)d_in[14]; const float* bm = (const float*)d_in[15];
    float* out = (float*)d_out;

    cudaFuncSetAttribute(gemm_tc_kernel,
                         cudaFuncAttributeMaxDynamicSharedMemorySize, SMEM_TOTAL);

    branch_kernel<<<M_DIM / 16, 512>>>(noise, W1, b1, W2, b2, W3, b3, W4, b4, W5, b5);
    trunk_kernel<<<N_DIM, 256>>>(coords, Wc, bc, Wm, bm);
    dim3 grid(N_DIM / 256, M_DIM / 128);
    gemm_tc_kernel<<<grid, 256, SMEM_TOTAL>>>(out);
}

// round 4
// speedup vs baseline: 2.0490x; 1.3846x over previous
#include <cuda_runtime.h>
#include <cuda_fp16.h>
#include <cstdint>

#define M_DIM 4096
#define N_DIM 8192
#define K_DIM 256

// ---------------------------------------------------------------------------
// Scratch: fp16 operands PRE-PACKED as m16n8k16 mma fragments.
// A half-index: tm*32768 + kt*2048 + i16*256 + lane*8 + reg*2 + klo
//   (reg = rowhalf + 2*khalf)
// B half-index: tn*65536 + kt*4096 + jp*256 + lane*8 + reg*2 + klo
//   (reg = n8sel*2 + khalf)
// ---------------------------------------------------------------------------
__device__ __align__(128) __half g_a_pk[M_DIM * K_DIM];   // 2 MB
__device__ __align__(128) __half g_b_pk[N_DIM * K_DIM];   // 4 MB
__device__ float g_bias[N_DIM];

// ---------------------------------------------------------------------------
// PTX helpers
// ---------------------------------------------------------------------------
__device__ __forceinline__ uint32_t smem_u32(const void* p) {
    uint32_t a;
    asm("{ .reg .u64 t; cvta.to.shared.u64 t, %1; cvt.u32.u64 %0, t; }" : "=r"(a) : "l"(p));
    return a;
}

#define MBARRIER_INIT(addr, cnt) \
    asm volatile("mbarrier.init.shared.b64 [%0], %1;" :: "r"(addr), "r"(cnt) : "memory")
#define MBARRIER_EXPECT_TX(addr, bytes) \
    asm volatile("mbarrier.arrive.expect_tx.shared.b64 _, [%0], %1;" :: "r"(addr), "r"(bytes) : "memory")
#define MBARRIER_ARRIVE(addr) \
    asm volatile("mbarrier.arrive.shared.b64 _, [%0];" :: "r"(addr) : "memory")

#define MBAR_WAIT(addr, parity) do {                                         \
    asm volatile("{\n\t.reg .pred P;\n\t"                                    \
        "W%=:\n\t"                                                           \
        "mbarrier.try_wait.parity.acquire.cta.shared::cta.b64 P, [%0], %1, 0x989680;\n\t" \
        "@P bra.uni D%=;\n\t bra.uni W%=;\n\tD%=:\n\t}"                      \
        :: "r"(addr), "r"(parity) : "memory");                               \
} while (0)

#define MBAR_WAIT_RELAXED(addr, parity) do {                                 \
    asm volatile("{\n\t.reg .pred P;\n\t"                                    \
        "W%=:\n\t"                                                           \
        "mbarrier.try_wait.parity.relaxed.cta.shared::cta.b64 P, [%0], %1, 0x989680;\n\t" \
        "@P bra.uni D%=;\n\t bra.uni W%=;\n\tD%=:\n\t}"                      \
        :: "r"(addr), "r"(parity) : "memory");                               \
} while (0)

__device__ __forceinline__ void bulk_g2s(uint32_t dst, const void* src, uint32_t bytes,
                                         uint32_t mbar) {
    asm volatile(
        "cp.async.bulk.shared::cluster.global.mbarrier::complete_tx::bytes [%0], [%1], %2, [%3];"
        :: "r"(dst), "l"(src), "r"(bytes), "r"(mbar) : "memory");
}

__device__ __forceinline__ void mma_f16(float* d, float4 a, float b0, float b1) {
    asm volatile(
        "mma.sync.aligned.m16n8k16.row.col.f32.f16.f16.f32 "
        "{%0,%1,%2,%3}, {%4,%5,%6,%7}, {%8,%9}, {%0,%1,%2,%3};"
        : "+f"(d[0]), "+f"(d[1]), "+f"(d[2]), "+f"(d[3])
        : "r"(__float_as_uint(a.x)), "r"(__float_as_uint(a.y)),
          "r"(__float_as_uint(a.z)), "r"(__float_as_uint(a.w)),
          "r"(__float_as_uint(b0)), "r"(__float_as_uint(b1)));
}

__device__ __forceinline__ uint32_t pack_h2(float lo, float hi) {
    __half2 h = __floats2half2_rn(lo, hi);
    return *(uint32_t*)&h;
}

// ---------------------------------------------------------------------------
// Kernel 1: Branch MLP. 128 blocks x 32 rows, 512 threads.
// Each warp runs TWO interleaved row chains (ILP). Dynamic smem.
// ---------------------------------------------------------------------------
#define BR_SW1   0
#define BR_SW2   (BR_SW1 + 128 * 32)
#define BR_SW3   (BR_SW2 + 32 * 32)
#define BR_SW4   (BR_SW3 + 32 * 32)
#define BR_SB    (BR_SW4 + 32 * 32)
#define BR_HBUF  (BR_SB + 4 * 32)
#define BR_OBUF  (BR_HBUF + 32 * 32)
#define BR_FLOATS (BR_OBUF + 32 * 256)
#define BR_SMEM  (BR_FLOATS * 4)

__global__ __launch_bounds__(512) void branch_kernel(
    const float* __restrict__ noise,
    const float* __restrict__ W1, const float* __restrict__ b1,
    const float* __restrict__ W2, const float* __restrict__ b2,
    const float* __restrict__ W3, const float* __restrict__ b3,
    const float* __restrict__ W4, const float* __restrict__ b4,
    const float* __restrict__ W5, const float* __restrict__ b5)
{
    extern __shared__ float sm[];
    float* sW1 = sm + BR_SW1;
    float* sW2 = sm + BR_SW2;
    float* sW3 = sm + BR_SW3;
    float* sW4 = sm + BR_SW4;
    float* sb  = sm + BR_SB;
    float* hbuf = sm + BR_HBUF;   // [32][32]
    float* obuf = sm + BR_OBUF;   // [32][256]

    int tid = threadIdx.x;
    for (int i = tid; i < 128 * 32; i += 512) sW1[i] = W1[i];
    for (int i = tid; i < 32 * 32; i += 512) {
        sW2[i] = W2[i]; sW3[i] = W3[i]; sW4[i] = W4[i];
    }
    if (tid < 32) {
        sb[tid] = b1[tid]; sb[32 + tid] = b2[tid];
        sb[64 + tid] = b3[tid]; sb[96 + tid] = b4[tid];
    }
    __syncthreads();

    int lane = tid & 31;
    int wid  = tid >> 5;
    int rbase = blockIdx.x * 32;
    int rowA = rbase + wid;
    int rowB = rowA + 16;

    const float* xa = noise + rowA * 128;
    const float* xb = noise + rowB * 128;
    float xa0 = xa[lane], xa1 = xa[lane + 32], xa2 = xa[lane + 64], xa3 = xa[lane + 96];
    float xb0 = xb[lane], xb1 = xb[lane + 32], xb2 = xb[lane + 64], xb3 = xb[lane + 96];

    // layer 1 (two rows, 8 accumulators)
    float aa0 = sb[lane], aa1 = 0.f, aa2 = 0.f, aa3 = 0.f;
    float ba0 = sb[lane], ba1 = 0.f, ba2 = 0.f, ba3 = 0.f;
    #pragma unroll
    for (int k = 0; k < 32; k++) {
        float w0 = sW1[k * 32 + lane];
        float w1 = sW1[(k + 32) * 32 + lane];
        float w2 = sW1[(k + 64) * 32 + lane];
        float w3 = sW1[(k + 96) * 32 + lane];
        aa0 = fmaf(__shfl_sync(~0u, xa0, k), w0, aa0);
        ba0 = fmaf(__shfl_sync(~0u, xb0, k), w0, ba0);
        aa1 = fmaf(__shfl_sync(~0u, xa1, k), w1, aa1);
        ba1 = fmaf(__shfl_sync(~0u, xb1, k), w1, ba1);
        aa2 = fmaf(__shfl_sync(~0u, xa2, k), w2, aa2);
        ba2 = fmaf(__shfl_sync(~0u, xb2, k), w2, ba2);
        aa3 = fmaf(__shfl_sync(~0u, xa3, k), w3, aa3);
        ba3 = fmaf(__shfl_sync(~0u, xb3, k), w3, ba3);
    }
    float hA = tanhf((aa0 + aa1) + (aa2 + aa3));
    float hB = tanhf((ba0 + ba1) + (ba2 + ba3));

    #pragma unroll
    for (int L = 0; L < 3; L++) {
        const float* W = (L == 0) ? sW2 : (L == 1) ? sW3 : sW4;
        float a = sb[32 * (L + 1) + lane];
        float b = a;
        #pragma unroll
        for (int k = 0; k < 32; k++) {
            float w = W[k * 32 + lane];
            a = fmaf(__shfl_sync(~0u, hA, k), w, a);
            b = fmaf(__shfl_sync(~0u, hB, k), w, b);
        }
        hA = tanhf(a);
        hB = tanhf(b);
    }
    hbuf[wid * 32 + lane] = hA;
    hbuf[(wid + 16) * 32 + lane] = hB;
    __syncthreads();

    // head: 32 -> 256, thread = (col c, half rh of 16 rows)
    int c  = tid & 255;
    int rh = tid >> 8;
    float o[16];
    float bias5 = b5[c];
    #pragma unroll
    for (int i = 0; i < 16; i++) o[i] = bias5;
    #pragma unroll
    for (int k = 0; k < 32; k++) {
        float w = W5[k * 256 + c];
        #pragma unroll
        for (int i = 0; i < 16; i++)
            o[i] = fmaf(hbuf[(rh * 16 + i) * 32 + k], w, o[i]);
    }
    #pragma unroll
    for (int i = 0; i < 16; i++)
        obuf[(rh * 16 + i) * 256 + c] = o[i];
    __syncthreads();

    // pack fp16 fragments: thread = (kt = tid>>5, lane), two i16 sub-blocks
    int kt = tid >> 5;
    int pl = tid & 31;
    int g = pl >> 2, t = pl & 3;
    int tm = rbase >> 7;
    int ib0 = (rbase & 127) >> 4;
    #pragma unroll
    for (int sub = 0; sub < 2; sub++) {
        uint32_t r32[4];
        #pragma unroll
        for (int reg = 0; reg < 4; reg++) {
            int half = reg & 1, khalf = reg >> 1;
            int row = sub * 16 + g + 8 * half;
            int kb  = kt * 16 + khalf * 8 + 2 * t;
            r32[reg] = pack_h2(obuf[row * 256 + kb], obuf[row * 256 + kb + 1]);
        }
        int hidx = tm * 32768 + kt * 2048 + (ib0 + sub) * 256 + pl * 8;
        *(uint4*)((char*)g_a_pk + hidx * 2) = make_uint4(r32[0], r32[1], r32[2], r32[3]);
    }
}

// ---------------------------------------------------------------------------
// Kernel 2: Trunk -> packed fp16 B fragments + bias. 512 blocks x 16 cols.
// ---------------------------------------------------------------------------
__global__ __launch_bounds__(256) void trunk_kernel(
    const float* __restrict__ coords,
    const float* __restrict__ Wc, const float* __restrict__ bc,
    const float* __restrict__ Wm, const float* __restrict__ bm)
{
    __shared__ float vbuf[16][256];
    int tid = threadIdx.x;
    int jbase = blockIdx.x * 16;

    #pragma unroll
    for (int it = 0; it < 16; it++) {
        int idx = it * 256 + tid;
        int j16 = idx >> 8, k = idx & 255;
        float c0 = coords[2 * (jbase + j16)];
        float c1 = coords[2 * (jbase + j16) + 1];
        vbuf[j16][k] = fmaf(c0, Wc[k], fmaf(c1, Wc[256 + k], bc[k]));
    }
    if (tid < 16) {
        float c0 = coords[2 * (jbase + tid)];
        float c1 = coords[2 * (jbase + tid) + 1];
        g_bias[jbase + tid] = fmaf(c0, Wm[0], fmaf(c1, Wm[1], bm[0]));
    }
    __syncthreads();

    int tn = jbase >> 8;
    int jp = (jbase & 255) >> 4;
    #pragma unroll
    for (int it = 0; it < 2; it++) {
        int slot = it * 256 + tid;
        int kt = slot >> 5, pl = slot & 31;
        int g = pl >> 2, t = pl & 3;
        uint32_t r32[4];
        #pragma unroll
        for (int reg = 0; reg < 4; reg++) {
            int n8 = reg >> 1, khalf = reg & 1;
            int cc = n8 * 8 + g;
            int kb = kt * 16 + khalf * 8 + 2 * t;
            r32[reg] = pack_h2(vbuf[cc][kb], vbuf[cc][kb + 1]);
        }
        int hidx = tn * 65536 + kt * 4096 + jp * 256 + pl * 8;
        *(uint4*)((char*)g_b_pk + hidx * 2) = make_uint4(r32[0], r32[1], r32[2], r32[3]);
    }
}

// ---------------------------------------------------------------------------
// Kernel 3: GEMM via mma.sync f16 m16n8k16, 4-stage bulk pipeline.
// CTA 128x256, 8 warps (2x4), warp tile 64x64.
// ---------------------------------------------------------------------------
#define A_STG 4096
#define B_STG 8192
#define SMEM_TOTAL (128 + 4 * (A_STG + B_STG))   // 49280

__global__ __launch_bounds__(256, 1) void gemm_tc_kernel(float* __restrict__ out) {
    extern __shared__ __align__(128) char smem[];
    uint32_t sbb   = smem_u32(smem);
    uint32_t fullb = sbb;
    uint32_t emptb = sbb + 32;
    const int AS_OFF = 128;
    const int BS_OFF = 128 + 4 * A_STG;

    int tid  = threadIdx.x;
    int wid  = tid >> 5, lane = tid & 31;
    int g    = lane >> 2, t = lane & 3;
    int bm0  = blockIdx.y * 128;
    int bn0  = blockIdx.x * 256;

    if (tid == 0) {
        #pragma unroll
        for (int s = 0; s < 4; s++) {
            MBARRIER_INIT(fullb + s * 8, 1);
            MBARRIER_INIT(emptb + s * 8, 8);
        }
    }
    __syncthreads();

    const __half* Ag = g_a_pk + blockIdx.y * 32768;
    const __half* Bg = g_b_pk + blockIdx.x * 65536;

    if (tid == 0) {
        #pragma unroll
        for (int s = 0; s < 4; s++) {
            MBARRIER_EXPECT_TX(fullb + s * 8, A_STG + B_STG);
            bulk_g2s(sbb + AS_OFF + s * A_STG, Ag + s * 2048, A_STG, fullb + s * 8);
            bulk_g2s(sbb + BS_OFF + s * B_STG, Bg + s * 4096, B_STG, fullb + s * 8);
        }
    }

    float acc[4][8][4];
    #pragma unroll
    for (int mt = 0; mt < 4; mt++)
        #pragma unroll
        for (int nt = 0; nt < 8; nt++)
            #pragma unroll
            for (int r = 0; r < 4; r++) acc[mt][nt][r] = 0.0f;

    int a_warp = (wid >> 2) * 2048;   // 4 i16 blocks x 512 B
    int b_warp = (wid & 3) * 2048;    // 4 jp blocks x 512 B

    for (int kt = 0; kt < 16; ++kt) {
        int s  = kt & 3;
        int ph = (kt >> 2) & 1;
        MBAR_WAIT(fullb + s * 8, ph);

        const char* As_s = smem + AS_OFF + s * A_STG + a_warp + lane * 16;
        const char* Bs_s = smem + BS_OFF + s * B_STG + b_warp + lane * 16;

        float4 afv[4], bfv[4];
        #pragma unroll
        for (int mt = 0; mt < 4; mt++)
            afv[mt] = *(const float4*)(As_s + mt * 512);
        #pragma unroll
        for (int p = 0; p < 4; p++)
            bfv[p] = *(const float4*)(Bs_s + p * 512);
        #pragma unroll
        for (int mt = 0; mt < 4; mt++)
            #pragma unroll
            for (int p = 0; p < 4; p++) {
                mma_f16(acc[mt][2 * p],     afv[mt], bfv[p].x, bfv[p].y);
                mma_f16(acc[mt][2 * p + 1], afv[mt], bfv[p].z, bfv[p].w);
            }

        if (lane == 0) MBARRIER_ARRIVE(emptb + s * 8);
        if (tid == 0 && kt < 12) {
            MBAR_WAIT_RELAXED(emptb + s * 8, ph);
            int ktp = kt + 4;
            MBARRIER_EXPECT_TX(fullb + s * 8, A_STG + B_STG);
            bulk_g2s(sbb + AS_OFF + s * A_STG, Ag + ktp * 2048, A_STG, fullb + s * 8);
            bulk_g2s(sbb + BS_OFF + s * B_STG, Bg + ktp * 4096, B_STG, fullb + s * 8);
        }
    }

    // epilogue: += bias[col], store float2 pairs
    int wm = (wid >> 2) * 64, wn = (wid & 3) * 64;
    #pragma unroll
    for (int nt = 0; nt < 8; nt++) {
        int col = bn0 + wn + (nt >> 1) * 16 + (nt & 1) * 8 + t * 2;
        float2 bb = *(const float2*)&g_bias[col];
        #pragma unroll
        for (int mt = 0; mt < 4; mt++) {
            int row = bm0 + wm + mt * 16 + g;
            float2 v0 = make_float2(acc[mt][nt][0] + bb.x, acc[mt][nt][1] + bb.y);
            float2 v1 = make_float2(acc[mt][nt][2] + bb.x, acc[mt][nt][3] + bb.y);
            *(float2*)&out[(size_t)row * N_DIM + col]       = v0;
            *(float2*)&out[(size_t)(row + 8) * N_DIM + col] = v1;
        }
    }
}

// ---------------------------------------------------------------------------
extern "C" void kernel_launch(void* const* d_in, const int* in_sizes, int n_in,
                              void* d_out, int out_size) {
    const float* noise  = (const float*)d_in[0];
    const float* coords = (const float*)d_in[1];
    const float* W1 = (const float*)d_in[2];  const float* b1 = (const float*)d_in[3];
    const float* W2 = (const float*)d_in[4];  const float* b2 = (const float*)d_in[5];
    const float* W3 = (const float*)d_in[6];  const float* b3 = (const float*)d_in[7];
    const float* W4 = (const float*)d_in[8];  const float* b4 = (const float*)d_in[9];
    const float* W5 = (const float*)d_in[10]; const float* b5 = (const float*)d_in[11];
    const float* Wc = (const float*)d_in[12]; const float* bc = (const float*)d_in[13];
    const float* Wm = (const float*)d_in[14]; const float* bm = (const float*)d_in[15];
    float* out = (float*)d_out;

    cudaFuncSetAttribute(gemm_tc_kernel,
                         cudaFuncAttributeMaxDynamicSharedMemorySize, SMEM_TOTAL);
    cudaFuncSetAttribute(branch_kernel,
                         cudaFuncAttributeMaxDynamicSharedMemorySize, BR_SMEM);

    branch_kernel<<<M_DIM / 32, 512, BR_SMEM>>>(noise, W1, b1, W2, b2, W3, b3, W4, b4, W5, b5);
    trunk_kernel<<<N_DIM / 16, 256>>>(coords, Wc, bc, Wm, bm);
    dim3 grid(N_DIM / 256, M_DIM / 128);
    gemm_tc_kernel<<<grid, 256, SMEM_TOTAL>>>(out);
}

// round 5
// speedup vs baseline: 3.7712x; 1.8405x over previous
#include <cuda_runtime.h>
#include <cstdint>

#define M_DIM 4096
#define N_DIM 8192

// Folded head: F[c][k] = sum_p W5[k,p] * G[c][p],  G = {Wc row0, Wc row1, bc}
// c3[c] = b5 . G[c]  (+ Wm[0], Wm[1], bm respectively)
__device__ float g_F[3][32];
__device__ float g_c3[3];
// Per-row coefficients: out[i,j] = P[i].x*c0[j] + P[i].y*c1[j] + P[i].z
__device__ __align__(16) float4 g_P[M_DIM];

// ---------------------------------------------------------------------------
// Kernel 0: fold W5/b5 through Wc/bc/Wm/bm. 1 block, 1024 threads.
// Warp w computes F[0..2][w]; warps 0..2 also compute c3[w].
// ---------------------------------------------------------------------------
__global__ __launch_bounds__(1024) void fold_kernel(
    const float* __restrict__ W5, const float* __restrict__ b5,
    const float* __restrict__ Wc, const float* __restrict__ bc,
    const float* __restrict__ Wm, const float* __restrict__ bm)
{
    int w = threadIdx.x >> 5, lane = threadIdx.x & 31;
    const float* G[3] = { Wc, Wc + 256, bc };

    // each lane handles 8 consecutive p
    int p0 = lane * 8;
    #pragma unroll
    for (int c = 0; c < 3; c++) {
        float s = 0.f;
        const float* wr = W5 + w * 256 + p0;
        const float* gr = G[c] + p0;
        #pragma unroll
        for (int q = 0; q < 8; q++) s = fmaf(wr[q], gr[q], s);
        #pragma unroll
        for (int off = 16; off; off >>= 1)
            s += __shfl_xor_sync(~0u, s, off);
        if (lane == 0) g_F[c][w] = s;
    }
    if (w < 3) {
        float s = 0.f;
        const float* gr = G[w] + p0;
        const float* br = b5 + p0;
        #pragma unroll
        for (int q = 0; q < 8; q++) s = fmaf(br[q], gr[q], s);
        #pragma unroll
        for (int off = 16; off; off >>= 1)
            s += __shfl_xor_sync(~0u, s, off);
        if (lane == 0) {
            float extra = (w == 0) ? Wm[0] : (w == 1) ? Wm[1] : bm[0];
            g_c3[w] = s + extra;
        }
    }
}

// ---------------------------------------------------------------------------
// Kernel 1: Branch MLP + folded head. 128 blocks x 32 rows, 512 threads.
// Each warp runs TWO interleaved row chains; lane = hidden unit.
// ---------------------------------------------------------------------------
__global__ __launch_bounds__(512) void branch_kernel(
    const float* __restrict__ noise,
    const float* __restrict__ W1, const float* __restrict__ b1,
    const float* __restrict__ W2, const float* __restrict__ b2,
    const float* __restrict__ W3, const float* __restrict__ b3,
    const float* __restrict__ W4, const float* __restrict__ b4)
{
    __shared__ float sW1[128 * 32];
    __shared__ float sW2[32 * 32];
    __shared__ float sW3[32 * 32];
    __shared__ float sW4[32 * 32];
    __shared__ float sb[4 * 32];
    __shared__ float sF[3][32];
    __shared__ float sc3[3];

    int tid = threadIdx.x;
    for (int i = tid; i < 128 * 32; i += 512) sW1[i] = W1[i];
    for (int i = tid; i < 32 * 32; i += 512) {
        sW2[i] = W2[i]; sW3[i] = W3[i]; sW4[i] = W4[i];
    }
    if (tid < 32) {
        sb[tid] = b1[tid]; sb[32 + tid] = b2[tid];
        sb[64 + tid] = b3[tid]; sb[96 + tid] = b4[tid];
        sF[0][tid] = g_F[0][tid];
        sF[1][tid] = g_F[1][tid];
        sF[2][tid] = g_F[2][tid];
        if (tid < 3) sc3[tid] = g_c3[tid];
    }
    __syncthreads();

    int lane = tid & 31;
    int wid  = tid >> 5;
    int rowA = blockIdx.x * 32 + wid;
    int rowB = rowA + 16;

    const float* xa = noise + rowA * 128;
    const float* xb = noise + rowB * 128;
    float xa0 = xa[lane], xa1 = xa[lane + 32], xa2 = xa[lane + 64], xa3 = xa[lane + 96];
    float xb0 = xb[lane], xb1 = xb[lane + 32], xb2 = xb[lane + 64], xb3 = xb[lane + 96];

    float aa0 = sb[lane], aa1 = 0.f, aa2 = 0.f, aa3 = 0.f;
    float ba0 = sb[lane], ba1 = 0.f, ba2 = 0.f, ba3 = 0.f;
    #pragma unroll
    for (int k = 0; k < 32; k++) {
        float w0 = sW1[k * 32 + lane];
        float w1 = sW1[(k + 32) * 32 + lane];
        float w2 = sW1[(k + 64) * 32 + lane];
        float w3 = sW1[(k + 96) * 32 + lane];
        aa0 = fmaf(__shfl_sync(~0u, xa0, k), w0, aa0);
        ba0 = fmaf(__shfl_sync(~0u, xb0, k), w0, ba0);
        aa1 = fmaf(__shfl_sync(~0u, xa1, k), w1, aa1);
        ba1 = fmaf(__shfl_sync(~0u, xb1, k), w1, ba1);
        aa2 = fmaf(__shfl_sync(~0u, xa2, k), w2, aa2);
        ba2 = fmaf(__shfl_sync(~0u, xb2, k), w2, ba2);
        aa3 = fmaf(__shfl_sync(~0u, xa3, k), w3, aa3);
        ba3 = fmaf(__shfl_sync(~0u, xb3, k), w3, ba3);
    }
    float hA = tanhf((aa0 + aa1) + (aa2 + aa3));
    float hB = tanhf((ba0 + ba1) + (ba2 + ba3));

    #pragma unroll
    for (int L = 0; L < 3; L++) {
        const float* W = (L == 0) ? sW2 : (L == 1) ? sW3 : sW4;
        float a = sb[32 * (L + 1) + lane];
        float b = a;
        #pragma unroll
        for (int k = 0; k < 32; k++) {
            float w = W[k * 32 + lane];
            a = fmaf(__shfl_sync(~0u, hA, k), w, a);
            b = fmaf(__shfl_sync(~0u, hB, k), w, b);
        }
        hA = tanhf(a);
        hB = tanhf(b);
    }

    // folded head: p_c = sum_k h[k] * F[c][k]  (+ c3[c])
    float F0 = sF[0][lane], F1 = sF[1][lane], F2 = sF[2][lane];
    float pa0 = hA * F0, pa1 = hA * F1, pa2 = hA * F2;
    float pb0 = hB * F0, pb1 = hB * F1, pb2 = hB * F2;
    #pragma unroll
    for (int off = 16; off; off >>= 1) {
        pa0 += __shfl_xor_sync(~0u, pa0, off);
        pa1 += __shfl_xor_sync(~0u, pa1, off);
        pa2 += __shfl_xor_sync(~0u, pa2, off);
        pb0 += __shfl_xor_sync(~0u, pb0, off);
        pb1 += __shfl_xor_sync(~0u, pb1, off);
        pb2 += __shfl_xor_sync(~0u, pb2, off);
    }
    if (lane == 0) {
        g_P[rowA] = make_float4(pa0 + sc3[0], pa1 + sc3[1], pa2 + sc3[2], 0.f);
        g_P[rowB] = make_float4(pb0 + sc3[0], pb1 + sc3[1], pb2 + sc3[2], 0.f);
    }
}

// ---------------------------------------------------------------------------
// Kernel 2: rank-3 outer product. out[i,j] = P[i].x*c0j + P[i].y*c1j + P[i].z
// Grid (8, 64): block owns 1024 cols x 64 rows. Coords held in registers,
// P chunk staged in smem. Pure coalesced 128MB write -> DRAM-bound.
// ---------------------------------------------------------------------------
__global__ __launch_bounds__(256) void out_kernel(
    const float* __restrict__ coords, float* __restrict__ out)
{
    __shared__ float4 sP[64];
    int tid = threadIdx.x;
    int r0  = blockIdx.y * 64;
    if (tid < 64) sP[tid] = g_P[r0 + tid];

    int j = blockIdx.x * 1024 + tid * 4;
    // coords interleaved (N,2): [c0_j, c1_j, c0_j+1, c1_j+1, ...]
    float4 ca = *(const float4*)(coords + 2 * j);
    float4 cb = *(const float4*)(coords + 2 * j + 4);
    __syncthreads();

    float* orow = out + (size_t)r0 * N_DIM + j;
    #pragma unroll 8
    for (int r = 0; r < 64; r++) {
        float4 P = sP[r];
        float4 v;
        v.x = fmaf(P.x, ca.x, fmaf(P.y, ca.y, P.z));
        v.y = fmaf(P.x, ca.z, fmaf(P.y, ca.w, P.z));
        v.z = fmaf(P.x, cb.x, fmaf(P.y, cb.y, P.z));
        v.w = fmaf(P.x, cb.z, fmaf(P.y, cb.w, P.z));
        *(float4*)(orow + (size_t)r * N_DIM) = v;
    }
}

// ---------------------------------------------------------------------------
extern "C" void kernel_launch(void* const* d_in, const int* in_sizes, int n_in,
                              void* d_out, int out_size) {
    const float* noise  = (const float*)d_in[0];
    const float* coords = (const float*)d_in[1];
    const float* W1 = (const float*)d_in[2];  const float* b1 = (const float*)d_in[3];
    const float* W2 = (const float*)d_in[4];  const float* b2 = (const float*)d_in[5];
    const float* W3 = (const float*)d_in[6];  const float* b3 = (const float*)d_in[7];
    const float* W4 = (const float*)d_in[8];  const float* b4 = (const float*)d_in[9];
    const float* W5 = (const float*)d_in[10]; const float* b5 = (const float*)d_in[11];
    const float* Wc = (const float*)d_in[12]; const float* bc = (const float*)d_in[13];
    const float* Wm = (const float*)d_in[14]; const float* bm = (const float*)d_in[15];
    float* out = (float*)d_out;

    fold_kernel<<<1, 1024>>>(W5, b5, Wc, bc, Wm, bm);
    branch_kernel<<<M_DIM / 32, 512>>>(noise, W1, b1, W2, b2, W3, b3, W4, b4);
    dim3 grid(N_DIM / 1024, M_DIM / 64);
    out_kernel<<<grid, 256>>>(coords, out);
}